// round 12
// baseline (speedup 1.0000x reference)
#include <cuda_runtime.h>
#include <cuda_bf16.h>
#include <math.h>
#include <stdint.h>

#define TT 3
#define RR 6
#define HH 4
#define DKK 64
#define DD 256
#define NN 50000
#define EE 400000
#define NPADMAX (NN + TT * 128)

typedef unsigned long long u64;

// ---- packed f32x2 helpers (for rel_transform) ----
__device__ __forceinline__ u64 splat2(float x) {
    u64 r;
    asm("mov.b64 %0, {%1, %1};" : "=l"(r) : "r"(__float_as_uint(x)));
    return r;
}
__device__ __forceinline__ void ffma2(u64& d, u64 a, u64 b) {
    asm("fma.rn.f32x2 %0, %1, %2, %3;" : "=l"(d) : "l"(a), "l"(b), "l"(d));
}
__device__ __forceinline__ float2 unpack2(u64 v) {
    unsigned int lo, hi;
    asm("mov.b64 {%0, %1}, %2;" : "=r"(lo), "=r"(hi) : "l"(v));
    return make_float2(__uint_as_float(lo), __uint_as_float(hi));
}

// ---- mma.sync / ldmatrix / cp.async helpers (sm_80-era, legal on sm_103) ----
__device__ __forceinline__ uint32_t smem_to_u32(const void* p) {
    uint32_t a;
    asm("{ .reg .u64 t; cvta.to.shared.u64 t, %1; cvt.u32.u64 %0, t; }" : "=r"(a) : "l"(p));
    return a;
}
__device__ __forceinline__ void ldsm4(uint32_t r[4], uint32_t addr) {
    asm volatile("ldmatrix.sync.aligned.m8n8.x4.shared.b16 {%0,%1,%2,%3}, [%4];"
        : "=r"(r[0]), "=r"(r[1]), "=r"(r[2]), "=r"(r[3]) : "r"(addr));
}
__device__ __forceinline__ void mma16816(float d[4], const uint32_t a[4], uint32_t b0, uint32_t b1) {
    asm volatile("mma.sync.aligned.m16n8k16.row.col.f32.bf16.bf16.f32 "
        "{%0,%1,%2,%3}, {%4,%5,%6,%7}, {%8,%9}, {%0,%1,%2,%3};"
        : "+f"(d[0]), "+f"(d[1]), "+f"(d[2]), "+f"(d[3])
        : "r"(a[0]), "r"(a[1]), "r"(a[2]), "r"(a[3]), "r"(b0), "r"(b1));
}
__device__ __forceinline__ void cp_async16(uint32_t dst, const void* src, bool valid) {
    int sz = valid ? 16 : 0;
    asm volatile("cp.async.cg.shared.global [%0], [%1], 16, %2;"
                 :: "r"(dst), "l"(src), "r"(sz));
}
#define CP_COMMIT() asm volatile("cp.async.commit_group;" ::: "memory")
#define CP_WAIT1()  asm volatile("cp.async.wait_group 1;" ::: "memory")
#define CP_WAIT0()  asm volatile("cp.async.wait_group 0;" ::: "memory")

// ---------------- scratch (device globals) ----------------
__device__ float g_k[(size_t)NN * DD];
__device__ float g_q[(size_t)NN * DD];
__device__ float g_v[(size_t)NN * DD];
__device__ float g_t[(size_t)NN * DD];
__device__ float g_trans[(size_t)NN * DD];
__device__ float g_krel[(size_t)RR * NN * DD];
__device__ float g_vrel[(size_t)RR * NN * DD];
__device__ float g_ex[(size_t)EE * HH];
__device__ float g_denom[(size_t)NN * RR * HH];
__device__ float g_invnrel[NN];
__device__ int   g_hasmsg[NN];
__device__ int   g_perm[NPADMAX];
__device__ int   g_cnt[TT];
__device__ int   g_cursor[TT];
__device__ int   g_padoff[TT + 1];
// bf16 hi/lo split buffers
__device__ __nv_bfloat16 g_xhi[(size_t)NN * DD];
__device__ __nv_bfloat16 g_xlo[(size_t)NN * DD];
__device__ __nv_bfloat16 g_thi[(size_t)NN * DD];
__device__ __nv_bfloat16 g_tlo[(size_t)NN * DD];
__device__ __nv_bfloat16 g_whiT[(size_t)4 * TT * DD * DD];   // [mat][t][j][k]  (W transposed)
__device__ __nv_bfloat16 g_wloT[(size_t)4 * TT * DD * DD];

// ---------------- type bucketing ----------------
__global__ void count_types(const int* __restrict__ nt, int n) {
    int i = blockIdx.x * blockDim.x + threadIdx.x;
    if (i < n) atomicAdd(&g_cnt[nt[i]], 1);
}
__global__ void make_offsets() {
    if (threadIdx.x == 0 && blockIdx.x == 0) {
        int off = 0;
        for (int t = 0; t < TT; t++) {
            g_padoff[t] = off;
            off += ((g_cnt[t] + 127) >> 7) << 7;
        }
        g_padoff[TT] = off;
    }
}
__global__ void scatter_perm(const int* __restrict__ nt, int n) {
    int i = blockIdx.x * blockDim.x + threadIdx.x;
    if (i < n) {
        int t = nt[i];
        int pos = g_padoff[t] + atomicAdd(&g_cursor[t], 1);
        g_perm[pos] = i;
    }
}

// ---------------- bf16 hi/lo split conversions ----------------
__global__ void conv_split(const float* __restrict__ src, const float* __restrict__ scale,
                           __nv_bfloat16* __restrict__ hi, __nv_bfloat16* __restrict__ lo, int n) {
    size_t i = (size_t)blockIdx.x * blockDim.x + threadIdx.x;
    if (i >= (size_t)n * 128) return;
    int node = (int)(i >> 7);
    float s = scale ? scale[node] : 1.0f;
    float2 f = ((const float2*)src)[i];
    f.x *= s; f.y *= s;
    __nv_bfloat16 h0 = __float2bfloat16(f.x);
    __nv_bfloat16 h1 = __float2bfloat16(f.y);
    __nv_bfloat16 l0 = __float2bfloat16(f.x - __bfloat162float(h0));
    __nv_bfloat16 l1 = __float2bfloat16(f.y - __bfloat162float(h1));
    hi[i * 2] = h0; hi[i * 2 + 1] = h1;
    lo[i * 2] = l0; lo[i * 2 + 1] = l1;
}

__global__ void conv_w(const float* __restrict__ Wk, const float* __restrict__ Wq,
                       const float* __restrict__ Wv, const float* __restrict__ Wa) {
    size_t i = (size_t)blockIdx.x * blockDim.x + threadIdx.x;
    if (i >= (size_t)4 * TT * DD * DD) return;
    int j = (int)(i % DD);
    size_t r = i / DD;
    int k = (int)(r % DD); r /= DD;
    int t = (int)(r % TT);
    int mat = (int)(r / TT);
    const float* src = (mat == 0) ? Wk : (mat == 1) ? Wq : (mat == 2) ? Wv : Wa;
    float w = src[((size_t)t * DD + k) * DD + j];
    __nv_bfloat16 h = __float2bfloat16(w);
    __nv_bfloat16 l = __float2bfloat16(w - __bfloat162float(h));
    size_t di = (((size_t)mat * TT + t) * DD + j) * DD + k;   // transposed [j][k]
    g_whiT[di] = h;
    g_wloT[di] = l;
}

// ---------------- tensor-core typed linear (mma.sync bf16x3 split precision)
// out[n] = A[n] @ W[type(n)] + bias[type(n)];  D = Ahi*Bhi + Ahi*Blo + Alo*Bhi (fp32 acc).
// BM=128, BN=128, BK=32, 8 warps (4M x 2N), warp tile 32x64, cp.async double-buffered.
struct TcArgs {
    const __nv_bfloat16* Ahi;      // [n][256]
    const __nv_bfloat16* Alo;
    const __nv_bfloat16* WhiT[3];  // [t][j][k]
    const __nv_bfloat16* WloT[3];
    const float* bias[3];
    float*       out[3];
};

// smem layout per buffer (48KB): A at 0, B at 24KB.
//   tile(split, kstep, row, kcol): split*12288 + kstep*6144 + row*48 + kcol*2  bytes
//   (row pad 24 bf16 = 48B -> ldmatrix conflict-free: r*48 mod 128 distinct for 8 rows)
#define STG_BUF   49152
#define STG_BOFF  24576
#define STG_SPLIT 12288
#define STG_KST   6144
#define ROWB      48

__global__ __launch_bounds__(256) void typed_gemm_tc(TcArgs args) {
    extern __shared__ char smem[];
    __shared__ int s_nodes[128];

    int row0 = blockIdx.x * 128;
    if (row0 >= g_padoff[TT]) return;
    int t = 0;
#pragma unroll
    for (int tt = 0; tt < TT - 1; tt++)
        if (row0 >= g_padoff[tt + 1]) t = tt + 1;

    uint32_t smem_base = smem_to_u32(smem);
    int tid = threadIdx.x;
    int lane = tid & 31;
    int wid = tid >> 5;
    int wy = wid & 3, wx = wid >> 2;

    if (tid < 128) s_nodes[tid] = g_perm[row0 + tid];
    __syncthreads();

    int z = blockIdx.z;
    int y0 = blockIdx.y * 128;
    const __nv_bfloat16* WhiT = args.WhiT[z] + ((size_t)t * DD + y0) * DD;
    const __nv_bfloat16* WloT = args.WloT[z] + ((size_t)t * DD + y0) * DD;

    // staging: slot s in [0,512): row=s>>2, kstep=(s>>1)&1, u4=s&1 -> 16B each
    int srow = tid >> 1;             // thread's two slots share row? no: use slot = tid + i*256
    (void)srow;
    int nodeCache[2];
    {
        int s0 = tid, s1 = tid + 256;
        nodeCache[0] = s_nodes[s0 >> 2];
        nodeCache[1] = s_nodes[s1 >> 2];
    }

    auto stage = [&](int chunk, int buf) {
        uint32_t sb = smem_base + buf * STG_BUF;
        int k0 = chunk * 32;
#pragma unroll
        for (int i = 0; i < 2; i++) {
            int slot = tid + i * 256;
            int row = slot >> 2, kstep = (slot >> 1) & 1, u4 = slot & 1;
            int node = nodeCache[i];
            int ksub = k0 + kstep * 16 + u4 * 8;
            uint32_t dA = sb + kstep * STG_KST + row * ROWB + u4 * 16;
            const __nv_bfloat16* pa = args.Ahi + ((size_t)(node < 0 ? 0 : node) * DD + ksub);
            const __nv_bfloat16* pl = args.Alo + ((size_t)(node < 0 ? 0 : node) * DD + ksub);
            cp_async16(dA, pa, node >= 0);
            cp_async16(dA + STG_SPLIT, pl, node >= 0);
            uint32_t dB = sb + STG_BOFF + kstep * STG_KST + row * ROWB + u4 * 16;
            cp_async16(dB, WhiT + (size_t)row * DD + ksub, true);
            cp_async16(dB + STG_SPLIT, WloT + (size_t)row * DD + ksub, true);
        }
    };

    float acc[2][8][4];
#pragma unroll
    for (int a = 0; a < 2; a++)
#pragma unroll
        for (int b = 0; b < 8; b++)
#pragma unroll
            for (int c = 0; c < 4; c++) acc[a][b][c] = 0.f;

    stage(0, 0);
    CP_COMMIT();

    // ldmatrix lane addressing
    int rsel = (lane & 7) + ((lane >> 3) & 1) * 8;
    int kc2 = ((lane >> 4) & 1) * 16;   // byte offset of k-col (8 bf16)

    int buf = 0;
    for (int c = 0; c < 8; c++) {
        if (c < 7) { stage(c + 1, buf ^ 1); CP_COMMIT(); }
        if (c < 7) CP_WAIT1(); else CP_WAIT0();
        __syncthreads();

        uint32_t sb = smem_base + buf * STG_BUF;
#pragma unroll
        for (int kstep = 0; kstep < 2; kstep++) {
            uint32_t ah[2][4], al[2][4], bh[4][4], bl[4][4];
            uint32_t baseA = sb + kstep * STG_KST;
            uint32_t baseB = sb + STG_BOFF + kstep * STG_KST;
#pragma unroll
            for (int mf = 0; mf < 2; mf++) {
                uint32_t ad = baseA + (uint32_t)((wy * 32 + mf * 16 + rsel) * ROWB) + kc2;
                ldsm4(ah[mf], ad);
                ldsm4(al[mf], ad + STG_SPLIT);
            }
#pragma unroll
            for (int p = 0; p < 4; p++) {
                uint32_t bd = baseB + (uint32_t)((wx * 64 + p * 16 + rsel) * ROWB) + kc2;
                ldsm4(bh[p], bd);
                ldsm4(bl[p], bd + STG_SPLIT);
            }
#pragma unroll
            for (int mf = 0; mf < 2; mf++)
#pragma unroll
                for (int p = 0; p < 4; p++)
#pragma unroll
                    for (int half = 0; half < 2; half++) {
                        float* d = acc[mf][p * 2 + half];
                        mma16816(d, ah[mf], bh[p][half], bh[p][2 + half]);
                        mma16816(d, ah[mf], bl[p][half], bl[p][2 + half]);
                        mma16816(d, al[mf], bh[p][half], bh[p][2 + half]);
                    }
        }
        __syncthreads();
        buf ^= 1;
    }

    // epilogue: fragment-direct scatter with bias
    const float* bias = args.bias[z] + (size_t)t * DD + y0;
    float* out = args.out[z];
#pragma unroll
    for (int mf = 0; mf < 2; mf++) {
        int mr = wy * 32 + mf * 16 + (lane >> 2);
        int nd0 = s_nodes[mr];
        int nd1 = s_nodes[mr + 8];
        float* o0 = (nd0 >= 0) ? (out + (size_t)nd0 * DD + y0) : nullptr;
        float* o1 = (nd1 >= 0) ? (out + (size_t)nd1 * DD + y0) : nullptr;
#pragma unroll
        for (int nf = 0; nf < 8; nf++) {
            int col = wx * 64 + nf * 8 + (lane & 3) * 2;
            float bx = bias[col], by = bias[col + 1];
            if (o0) *(float2*)(o0 + col) = make_float2(acc[mf][nf][0] + bx, acc[mf][nf][1] + by);
            if (o1) *(float2*)(o1 + col) = make_float2(acc[mf][nf][2] + bx, acc[mf][nf][3] + by);
        }
    }
}

// ---------------- relation transforms (FFMA2 GEMM, A-tile reused across relations) ------
__global__ __launch_bounds__(256) void rel_transform(const float* __restrict__ Watt,
                                                     const float* __restrict__ Wmsg,
                                                     int n) {
    extern __shared__ float sm[];
    float (*As)[264] = (float (*)[264])sm;
    float (*Bs)[64]  = (float (*)[64])(sm + 64 * 264);

    int tid = threadIdx.x;
    int z = blockIdx.z;
    int phase = z >> 2;
    int h = z & 3;

    const float* src   = phase ? g_v : g_k;
    const float* Wbase = phase ? Wmsg : Watt;
    float* dst         = phase ? g_vrel : g_krel;

    int row0 = blockIdx.x * 256;
    int tx = tid & 7, ty = tid >> 3;

    {
        int node = row0 + tid;
        if (node < n) {
            const float* Arow = src + (size_t)node * DD + h * DKK;
#pragma unroll
            for (int i = 0; i < 16; i++) {
                float4 v = *(const float4*)(Arow + i * 4);
                As[i * 4 + 0][tid] = v.x;
                As[i * 4 + 1][tid] = v.y;
                As[i * 4 + 2][tid] = v.z;
                As[i * 4 + 3][tid] = v.w;
            }
        } else {
#pragma unroll
            for (int i = 0; i < 64; i++) As[i][tid] = 0.f;
        }
    }

    for (int r = 0; r < RR; r++) {
        __syncthreads();
        const float* Wp = Wbase + ((size_t)r * HH + h) * DKK * DKK;
        for (int i = tid; i < DKK * DKK / 4; i += 256)
            ((float4*)Bs)[i] = ((const float4*)Wp)[i];
        __syncthreads();

        u64 acc[8][4];
#pragma unroll
        for (int i = 0; i < 8; i++)
#pragma unroll
            for (int j = 0; j < 4; j++) acc[i][j] = 0ull;

#pragma unroll 16
        for (int kk = 0; kk < DKK; kk++) {
            float4 a0 = *(float4*)&As[kk][ty * 8];
            float4 a1 = *(float4*)&As[kk][ty * 8 + 4];
            ulonglong2 blv = *(ulonglong2*)&Bs[kk][tx * 8];
            ulonglong2 bhv = *(ulonglong2*)&Bs[kk][tx * 8 + 4];
            u64 bb[4] = {blv.x, blv.y, bhv.x, bhv.y};
            float a[8] = {a0.x, a0.y, a0.z, a0.w, a1.x, a1.y, a1.z, a1.w};
#pragma unroll
            for (int i = 0; i < 8; i++) {
                u64 aa = splat2(a[i]);
                ffma2(acc[i][0], aa, bb[0]);
                ffma2(acc[i][1], aa, bb[1]);
                ffma2(acc[i][2], aa, bb[2]);
                ffma2(acc[i][3], aa, bb[3]);
            }
        }

#pragma unroll
        for (int i = 0; i < 8; i++) {
            int node = row0 + ty * 8 + i;
            if (node < n) {
                float* o = dst + ((size_t)r * n + node) * DD + h * DKK + tx * 8;
                float2 p0 = unpack2(acc[i][0]);
                float2 p1 = unpack2(acc[i][1]);
                float2 p2 = unpack2(acc[i][2]);
                float2 p3 = unpack2(acc[i][3]);
                *(float4*)o       = make_float4(p0.x, p0.y, p1.x, p1.y);
                *(float4*)(o + 4) = make_float4(p2.x, p2.y, p3.x, p3.y);
            }
        }
    }
}

// ---------------- edge pass 1 ----------------
__global__ void edge_att(const int* __restrict__ esrc, const int* __restrict__ edst,
                         const int* __restrict__ etype, const float* __restrict__ rel_pri,
                         int ne, int n) {
    int e = blockIdx.x * 8 + (threadIdx.x >> 5);
    if (e >= ne) return;
    int L = threadIdx.x & 31;
    int src = esrc[e], dst = edst[e], r = etype[e];

    const float4* qp = (const float4*)(g_q + (size_t)dst * DD) + L * 2;
    const float4* kp = (const float4*)(g_krel + ((size_t)r * n + src) * DD) + L * 2;
    float4 q0 = qp[0], q1 = qp[1];
    float4 k0 = kp[0], k1 = kp[1];
    float s = q0.x * k0.x + q0.y * k0.y + q0.z * k0.z + q0.w * k0.w
            + q1.x * k1.x + q1.y * k1.y + q1.z * k1.z + q1.w * k1.w;
    s += __shfl_xor_sync(0xffffffffu, s, 1);
    s += __shfl_xor_sync(0xffffffffu, s, 2);
    s += __shfl_xor_sync(0xffffffffu, s, 4);
    if ((L & 7) == 0) {
        int h = L >> 3;
        float att = s * rel_pri[r * HH + h] * 0.125f;
        float ex = expf(att);
        g_ex[(size_t)e * HH + h] = ex;
        atomicAdd(&g_denom[((size_t)dst * RR + r) * HH + h], ex);
    }
}

// ---------------- edge pass 2 ----------------
__global__ void edge_aggregate(const int* __restrict__ esrc, const int* __restrict__ edst,
                               const int* __restrict__ etype, int ne, int n) {
    int e = blockIdx.x * 8 + (threadIdx.x >> 5);
    if (e >= ne) return;
    int L = threadIdx.x & 31;
    int src = esrc[e], dst = edst[e], r = etype[e];
    int h = L >> 3;
    float w = g_ex[(size_t)e * HH + h] / g_denom[((size_t)dst * RR + r) * HH + h];

    const float4* vp = (const float4*)(g_vrel + ((size_t)r * n + src) * DD) + L * 2;
    float4 v0 = vp[0], v1 = vp[1];
    float* tp = g_t + (size_t)dst * DD + L * 8;
    asm volatile("red.global.add.v4.f32 [%0], {%1,%2,%3,%4};"
                 :: "l"(tp), "f"(v0.x * w), "f"(v0.y * w), "f"(v0.z * w), "f"(v0.w * w)
                 : "memory");
    asm volatile("red.global.add.v4.f32 [%0], {%1,%2,%3,%4};"
                 :: "l"(tp + 4), "f"(v1.x * w), "f"(v1.y * w), "f"(v1.z * w), "f"(v1.w * w)
                 : "memory");
}

// ---------------- per-node nrel ----------------
__global__ void node_nrel(int n) {
    int i = blockIdx.x * blockDim.x + threadIdx.x;
    if (i >= n) return;
    int c = 0;
#pragma unroll
    for (int r = 0; r < RR; r++)
        c += (g_denom[((size_t)i * RR + r) * HH] > 0.f) ? 1 : 0;
    g_hasmsg[i] = (c > 0) ? 1 : 0;
    g_invnrel[i] = 1.0f / (float)(c > 0 ? c : 1);
}

// ---------------- final: gated residual + LN + passthrough ----------------
__global__ void finalize(const float* __restrict__ x, const float* __restrict__ skip,
                         const float* __restrict__ ln_g, const float* __restrict__ ln_b,
                         const int* __restrict__ nt, float* __restrict__ out, int n) {
    int node = blockIdx.x * 8 + (threadIdx.x >> 5);
    if (node >= n) return;
    int L = threadIdx.x & 31;
    int t = nt[node];
    float alpha = 1.0f / (1.0f + expf(-skip[t]));
    float beta = 1.0f - alpha;

    const float4* xp = (const float4*)(x + (size_t)node * DD) + L * 2;
    const float4* tp = (const float4*)(g_trans + (size_t)node * DD) + L * 2;
    float4 x0 = xp[0], x1 = xp[1];
    float4 t0 = tp[0], t1 = tp[1];

    float o[8];
    o[0] = t0.x * alpha + x0.x * beta;
    o[1] = t0.y * alpha + x0.y * beta;
    o[2] = t0.z * alpha + x0.z * beta;
    o[3] = t0.w * alpha + x0.w * beta;
    o[4] = t1.x * alpha + x1.x * beta;
    o[5] = t1.y * alpha + x1.y * beta;
    o[6] = t1.z * alpha + x1.z * beta;
    o[7] = t1.w * alpha + x1.w * beta;

    float s = 0.f, s2 = 0.f;
#pragma unroll
    for (int j = 0; j < 8; j++) { s += o[j]; s2 += o[j] * o[j]; }
#pragma unroll
    for (int off = 16; off > 0; off >>= 1) {
        s  += __shfl_xor_sync(0xffffffffu, s, off);
        s2 += __shfl_xor_sync(0xffffffffu, s2, off);
    }
    float mu = s * (1.0f / DD);
    float var = s2 * (1.0f / DD) - mu * mu;
    float rstd = rsqrtf(var + 1e-5f);

    float4 r0, r1;
    if (g_hasmsg[node]) {
        const float4* gp = (const float4*)(ln_g + (size_t)t * DD) + L * 2;
        const float4* bp = (const float4*)(ln_b + (size_t)t * DD) + L * 2;
        float4 g0 = gp[0], g1 = gp[1];
        float4 b0 = bp[0], b1 = bp[1];
        r0.x = (o[0] - mu) * rstd * g0.x + b0.x;
        r0.y = (o[1] - mu) * rstd * g0.y + b0.y;
        r0.z = (o[2] - mu) * rstd * g0.z + b0.z;
        r0.w = (o[3] - mu) * rstd * g0.w + b0.w;
        r1.x = (o[4] - mu) * rstd * g1.x + b1.x;
        r1.y = (o[5] - mu) * rstd * g1.y + b1.y;
        r1.z = (o[6] - mu) * rstd * g1.z + b1.z;
        r1.w = (o[7] - mu) * rstd * g1.w + b1.w;
    } else {
        r0 = x0; r1 = x1;
    }
    float4* op = (float4*)(out + (size_t)node * DD) + L * 2;
    op[0] = r0;
    op[1] = r1;
}

// ---------------- host launcher ----------------
extern "C" void kernel_launch(void* const* d_in, const int* in_sizes, int n_in,
                              void* d_out, int out_size) {
    const float* x       = (const float*)d_in[0];
    const float* Wk      = (const float*)d_in[1];
    const float* bk      = (const float*)d_in[2];
    const float* Wq      = (const float*)d_in[3];
    const float* bq      = (const float*)d_in[4];
    const float* Wv      = (const float*)d_in[5];
    const float* bv      = (const float*)d_in[6];
    const float* Wa      = (const float*)d_in[7];
    const float* ba      = (const float*)d_in[8];
    const float* rel_pri = (const float*)d_in[9];
    const float* rel_att = (const float*)d_in[10];
    const float* rel_msg = (const float*)d_in[11];
    const float* skip    = (const float*)d_in[12];
    const float* ln_g    = (const float*)d_in[13];
    const float* ln_b    = (const float*)d_in[14];
    const int* node_type = (const int*)d_in[15];
    const int* edge_src  = (const int*)d_in[16];
    const int* edge_dst  = (const int*)d_in[17];
    const int* edge_type = (const int*)d_in[18];

    int n  = in_sizes[0] / DD;
    int ne = in_sizes[16];
    if (n > NN || ne > EE) return;

    void *p_cnt, *p_cursor, *p_perm, *p_denom, *p_t;
    void *p_k, *p_q, *p_v, *p_trans, *p_invnrel;
    void *p_xhi, *p_xlo, *p_thi, *p_tlo, *p_whiT, *p_wloT;
    cudaGetSymbolAddress(&p_cnt, g_cnt);
    cudaGetSymbolAddress(&p_cursor, g_cursor);
    cudaGetSymbolAddress(&p_perm, g_perm);
    cudaGetSymbolAddress(&p_denom, g_denom);
    cudaGetSymbolAddress(&p_t, g_t);
    cudaGetSymbolAddress(&p_k, g_k);
    cudaGetSymbolAddress(&p_q, g_q);
    cudaGetSymbolAddress(&p_v, g_v);
    cudaGetSymbolAddress(&p_trans, g_trans);
    cudaGetSymbolAddress(&p_invnrel, g_invnrel);
    cudaGetSymbolAddress(&p_xhi, g_xhi);
    cudaGetSymbolAddress(&p_xlo, g_xlo);
    cudaGetSymbolAddress(&p_thi, g_thi);
    cudaGetSymbolAddress(&p_tlo, g_tlo);
    cudaGetSymbolAddress(&p_whiT, g_whiT);
    cudaGetSymbolAddress(&p_wloT, g_wloT);

    cudaMemsetAsync(p_cnt, 0, sizeof(int) * TT);
    cudaMemsetAsync(p_cursor, 0, sizeof(int) * TT);
    cudaMemsetAsync(p_perm, 0xFF, sizeof(int) * NPADMAX);
    cudaMemsetAsync(p_denom, 0, sizeof(float) * (size_t)n * RR * HH);
    cudaMemsetAsync(p_t, 0, sizeof(float) * (size_t)n * DD);

    // conversions + bucketing
    conv_w<<<(4 * TT * DD * DD + 255) / 256, 256>>>(Wk, Wq, Wv, Wa);
    conv_split<<<(int)(((size_t)n * 128 + 255) / 256), 256>>>(x, nullptr,
        (__nv_bfloat16*)p_xhi, (__nv_bfloat16*)p_xlo, n);
    count_types<<<(n + 255) / 256, 256>>>(node_type, n);
    make_offsets<<<1, 1>>>();
    scatter_perm<<<(n + 255) / 256, 256>>>(node_type, n);

    cudaFuncSetAttribute(typed_gemm_tc, cudaFuncAttributeMaxDynamicSharedMemorySize, 2 * STG_BUF);

    // fused KQV typed linears on tensor cores (mma.sync)
    TcArgs a1;
    a1.Ahi = (const __nv_bfloat16*)p_xhi;
    a1.Alo = (const __nv_bfloat16*)p_xlo;
    for (int m = 0; m < 3; m++) {
        a1.WhiT[m] = (const __nv_bfloat16*)p_whiT + (size_t)m * TT * DD * DD;
        a1.WloT[m] = (const __nv_bfloat16*)p_wloT + (size_t)m * TT * DD * DD;
    }
    a1.bias[0] = bk; a1.bias[1] = bq; a1.bias[2] = bv;
    a1.out[0] = (float*)p_k; a1.out[1] = (float*)p_q; a1.out[2] = (float*)p_v;
    dim3 grid1((n + 127) / 128 + TT, DD / 128, 3);
    typed_gemm_tc<<<grid1, 256, 2 * STG_BUF>>>(a1);

    // relation transforms
    int relSmem = (64 * 264 + 64 * 64) * sizeof(float);
    cudaFuncSetAttribute(rel_transform, cudaFuncAttributeMaxDynamicSharedMemorySize, relSmem);
    dim3 gridR((n + 255) / 256, 1, 2 * HH);
    rel_transform<<<gridR, 256, relSmem>>>(rel_att, rel_msg, n);

    // edge passes
    edge_att<<<(ne + 7) / 8, 256>>>(edge_src, edge_dst, edge_type, rel_pri, ne, n);
    edge_aggregate<<<(ne + 7) / 8, 256>>>(edge_src, edge_dst, edge_type, ne, n);
    node_nrel<<<(n + 255) / 256, 256>>>(n);

    // output typed linear (invnrel folded into t conversion)
    conv_split<<<(int)(((size_t)n * 128 + 255) / 256), 256>>>((const float*)p_t, (const float*)p_invnrel,
        (__nv_bfloat16*)p_thi, (__nv_bfloat16*)p_tlo, n);
    TcArgs a2;
    a2.Ahi = (const __nv_bfloat16*)p_thi;
    a2.Alo = (const __nv_bfloat16*)p_tlo;
    for (int m = 0; m < 3; m++) {
        a2.WhiT[m] = (const __nv_bfloat16*)p_whiT + (size_t)3 * TT * DD * DD;
        a2.WloT[m] = (const __nv_bfloat16*)p_wloT + (size_t)3 * TT * DD * DD;
        a2.bias[m] = ba;
        a2.out[m] = (float*)p_trans;
    }
    dim3 grid2((n + 127) / 128 + TT, DD / 128, 1);
    typed_gemm_tc<<<grid2, 256, 2 * STG_BUF>>>(a2);

    // gated residual + LN + passthrough
    finalize<<<(n + 7) / 8, 256>>>(x, skip, ln_g, ln_b, node_type, (float*)d_out, n);
}

// round 13
// speedup vs baseline: 1.4877x; 1.4877x over previous
#include <cuda_runtime.h>
#include <cuda_bf16.h>
#include <math.h>
#include <stdint.h>

#define TT 3
#define RR 6
#define HH 4
#define DKK 64
#define DD 256
#define NN 50000
#define EE 400000
#define NPADMAX (NN + TT * 128)

typedef unsigned long long u64;

// ---- packed f32x2 helpers (for rel_transform) ----
__device__ __forceinline__ u64 splat2(float x) {
    u64 r;
    asm("mov.b64 %0, {%1, %1};" : "=l"(r) : "r"(__float_as_uint(x)));
    return r;
}
__device__ __forceinline__ void ffma2(u64& d, u64 a, u64 b) {
    asm("fma.rn.f32x2 %0, %1, %2, %3;" : "=l"(d) : "l"(a), "l"(b), "l"(d));
}
__device__ __forceinline__ float2 unpack2(u64 v) {
    unsigned int lo, hi;
    asm("mov.b64 {%0, %1}, %2;" : "=r"(lo), "=r"(hi) : "l"(v));
    return make_float2(__uint_as_float(lo), __uint_as_float(hi));
}

// ---- mma.sync / ldmatrix / cp.async helpers (sm_80-era, legal on sm_103) ----
__device__ __forceinline__ uint32_t smem_to_u32(const void* p) {
    uint32_t a;
    asm("{ .reg .u64 t; cvta.to.shared.u64 t, %1; cvt.u32.u64 %0, t; }" : "=r"(a) : "l"(p));
    return a;
}
__device__ __forceinline__ void ldsm4(uint32_t r[4], uint32_t addr) {
    asm volatile("ldmatrix.sync.aligned.m8n8.x4.shared.b16 {%0,%1,%2,%3}, [%4];"
        : "=r"(r[0]), "=r"(r[1]), "=r"(r[2]), "=r"(r[3]) : "r"(addr));
}
__device__ __forceinline__ void mma16816(float d[4], const uint32_t a[4], uint32_t b0, uint32_t b1) {
    asm volatile("mma.sync.aligned.m16n8k16.row.col.f32.bf16.bf16.f32 "
        "{%0,%1,%2,%3}, {%4,%5,%6,%7}, {%8,%9}, {%0,%1,%2,%3};"
        : "+f"(d[0]), "+f"(d[1]), "+f"(d[2]), "+f"(d[3])
        : "r"(a[0]), "r"(a[1]), "r"(a[2]), "r"(a[3]), "r"(b0), "r"(b1));
}
__device__ __forceinline__ void cp_async16(uint32_t dst, const void* src, bool valid) {
    int sz = valid ? 16 : 0;
    asm volatile("cp.async.cg.shared.global [%0], [%1], 16, %2;"
                 :: "r"(dst), "l"(src), "r"(sz));
}
#define CP_COMMIT() asm volatile("cp.async.commit_group;" ::: "memory")
#define CP_WAIT1()  asm volatile("cp.async.wait_group 1;" ::: "memory")
#define CP_WAIT0()  asm volatile("cp.async.wait_group 0;" ::: "memory")

// ---------------- scratch (device globals) ----------------
__device__ float g_k[(size_t)NN * DD];
__device__ float g_q[(size_t)NN * DD];
__device__ float g_v[(size_t)NN * DD];
__device__ float g_t[(size_t)NN * DD];
__device__ float g_trans[(size_t)NN * DD];
__device__ float g_krel[(size_t)RR * NN * DD];
__device__ float g_vrel[(size_t)RR * NN * DD];
__device__ float g_ex[(size_t)EE * HH];
__device__ float g_denom[(size_t)NN * RR * HH];
__device__ float g_invnrel[NN];
__device__ int   g_hasmsg[NN];
__device__ int   g_perm[NPADMAX];
__device__ int   g_cnt[TT];
__device__ int   g_cursor[TT];
__device__ int   g_padoff[TT + 1];
// bf16 hi/lo split buffers
__device__ __nv_bfloat16 g_xhi[(size_t)NN * DD];
__device__ __nv_bfloat16 g_xlo[(size_t)NN * DD];
__device__ __nv_bfloat16 g_thi[(size_t)NN * DD];
__device__ __nv_bfloat16 g_tlo[(size_t)NN * DD];
__device__ __nv_bfloat16 g_whiT[(size_t)4 * TT * DD * DD];   // [mat][t][j][k]  (W transposed)
__device__ __nv_bfloat16 g_wloT[(size_t)4 * TT * DD * DD];

// ---------------- type bucketing ----------------
__global__ void count_types(const int* __restrict__ nt, int n) {
    int i = blockIdx.x * blockDim.x + threadIdx.x;
    if (i < n) atomicAdd(&g_cnt[nt[i]], 1);
}
__global__ void make_offsets() {
    if (threadIdx.x == 0 && blockIdx.x == 0) {
        int off = 0;
        for (int t = 0; t < TT; t++) {
            g_padoff[t] = off;
            off += ((g_cnt[t] + 127) >> 7) << 7;
        }
        g_padoff[TT] = off;
    }
}
__global__ void scatter_perm(const int* __restrict__ nt, int n) {
    int i = blockIdx.x * blockDim.x + threadIdx.x;
    if (i < n) {
        int t = nt[i];
        int pos = g_padoff[t] + atomicAdd(&g_cursor[t], 1);
        g_perm[pos] = i;
    }
}

// ---------------- bf16 hi/lo split conversions ----------------
__global__ void conv_split(const float* __restrict__ src, const float* __restrict__ scale,
                           __nv_bfloat16* __restrict__ hi, __nv_bfloat16* __restrict__ lo, int n) {
    size_t i = (size_t)blockIdx.x * blockDim.x + threadIdx.x;
    if (i >= (size_t)n * 128) return;
    int node = (int)(i >> 7);
    float s = scale ? scale[node] : 1.0f;
    float2 f = ((const float2*)src)[i];
    f.x *= s; f.y *= s;
    __nv_bfloat16 h0 = __float2bfloat16(f.x);
    __nv_bfloat16 h1 = __float2bfloat16(f.y);
    __nv_bfloat16 l0 = __float2bfloat16(f.x - __bfloat162float(h0));
    __nv_bfloat16 l1 = __float2bfloat16(f.y - __bfloat162float(h1));
    hi[i * 2] = h0; hi[i * 2 + 1] = h1;
    lo[i * 2] = l0; lo[i * 2 + 1] = l1;
}

__global__ void conv_w(const float* __restrict__ Wk, const float* __restrict__ Wq,
                       const float* __restrict__ Wv, const float* __restrict__ Wa) {
    size_t i = (size_t)blockIdx.x * blockDim.x + threadIdx.x;
    if (i >= (size_t)4 * TT * DD * DD) return;
    int j = (int)(i % DD);
    size_t r = i / DD;
    int k = (int)(r % DD); r /= DD;
    int t = (int)(r % TT);
    int mat = (int)(r / TT);
    const float* src = (mat == 0) ? Wk : (mat == 1) ? Wq : (mat == 2) ? Wv : Wa;
    float w = src[((size_t)t * DD + k) * DD + j];
    __nv_bfloat16 h = __float2bfloat16(w);
    __nv_bfloat16 l = __float2bfloat16(w - __bfloat162float(h));
    size_t di = (((size_t)mat * TT + t) * DD + j) * DD + k;   // transposed [j][k]
    g_whiT[di] = h;
    g_wloT[di] = l;
}

// ---------------- tensor-core typed linear (mma.sync bf16x3 split precision)
// out[n] = A[n] @ W[type(n)] + bias[type(n)];  D = Ahi*Bhi + Ahi*Blo + Alo*Bhi (fp32 acc).
// BM=128, BN=128, BK=32, 8 warps (4M x 2N), warp tile 32x64, cp.async double-buffered.
struct TcArgs {
    const __nv_bfloat16* Ahi;      // [n][256]
    const __nv_bfloat16* Alo;
    const __nv_bfloat16* WhiT[3];  // [t][j][k]
    const __nv_bfloat16* WloT[3];
    const float* bias[3];
    float*       out[3];
};

// smem layout per buffer (48KB): A at 0, B at 24KB.
//   tile(split, kstep, row, kcol): split*12288 + kstep*6144 + row*48 + kcol*2  bytes
//   (row pad 24 bf16 = 48B -> ldmatrix conflict-free: r*48 mod 128 distinct for 8 rows)
#define STG_BUF   49152
#define STG_BOFF  24576
#define STG_SPLIT 12288
#define STG_KST   6144
#define ROWB      48

__global__ __launch_bounds__(256) void typed_gemm_tc(TcArgs args) {
    extern __shared__ char smem[];
    __shared__ int s_nodes[128];

    int row0 = blockIdx.x * 128;
    if (row0 >= g_padoff[TT]) return;
    int t = 0;
#pragma unroll
    for (int tt = 0; tt < TT - 1; tt++)
        if (row0 >= g_padoff[tt + 1]) t = tt + 1;

    uint32_t smem_base = smem_to_u32(smem);
    int tid = threadIdx.x;
    int lane = tid & 31;
    int wid = tid >> 5;
    int wy = wid & 3, wx = wid >> 2;

    if (tid < 128) s_nodes[tid] = g_perm[row0 + tid];
    __syncthreads();

    int z = blockIdx.z;
    int y0 = blockIdx.y * 128;
    const __nv_bfloat16* WhiT = args.WhiT[z] + ((size_t)t * DD + y0) * DD;
    const __nv_bfloat16* WloT = args.WloT[z] + ((size_t)t * DD + y0) * DD;

    // staging: slot s in [0,512): row=s>>2, kstep=(s>>1)&1, u4=s&1 -> 16B each
    int srow = tid >> 1;             // thread's two slots share row? no: use slot = tid + i*256
    (void)srow;
    int nodeCache[2];
    {
        int s0 = tid, s1 = tid + 256;
        nodeCache[0] = s_nodes[s0 >> 2];
        nodeCache[1] = s_nodes[s1 >> 2];
    }

    auto stage = [&](int chunk, int buf) {
        uint32_t sb = smem_base + buf * STG_BUF;
        int k0 = chunk * 32;
#pragma unroll
        for (int i = 0; i < 2; i++) {
            int slot = tid + i * 256;
            int row = slot >> 2, kstep = (slot >> 1) & 1, u4 = slot & 1;
            int node = nodeCache[i];
            int ksub = k0 + kstep * 16 + u4 * 8;
            uint32_t dA = sb + kstep * STG_KST + row * ROWB + u4 * 16;
            const __nv_bfloat16* pa = args.Ahi + ((size_t)(node < 0 ? 0 : node) * DD + ksub);
            const __nv_bfloat16* pl = args.Alo + ((size_t)(node < 0 ? 0 : node) * DD + ksub);
            cp_async16(dA, pa, node >= 0);
            cp_async16(dA + STG_SPLIT, pl, node >= 0);
            uint32_t dB = sb + STG_BOFF + kstep * STG_KST + row * ROWB + u4 * 16;
            cp_async16(dB, WhiT + (size_t)row * DD + ksub, true);
            cp_async16(dB + STG_SPLIT, WloT + (size_t)row * DD + ksub, true);
        }
    };

    float acc[2][8][4];
#pragma unroll
    for (int a = 0; a < 2; a++)
#pragma unroll
        for (int b = 0; b < 8; b++)
#pragma unroll
            for (int c = 0; c < 4; c++) acc[a][b][c] = 0.f;

    stage(0, 0);
    CP_COMMIT();

    // ldmatrix lane addressing
    int rsel = (lane & 7) + ((lane >> 3) & 1) * 8;
    int kc2 = ((lane >> 4) & 1) * 16;   // byte offset of k-col (8 bf16)

    int buf = 0;
    for (int c = 0; c < 8; c++) {
        if (c < 7) { stage(c + 1, buf ^ 1); CP_COMMIT(); }
        if (c < 7) CP_WAIT1(); else CP_WAIT0();
        __syncthreads();

        uint32_t sb = smem_base + buf * STG_BUF;
#pragma unroll
        for (int kstep = 0; kstep < 2; kstep++) {
            uint32_t ah[2][4], al[2][4], bh[4][4], bl[4][4];
            uint32_t baseA = sb + kstep * STG_KST;
            uint32_t baseB = sb + STG_BOFF + kstep * STG_KST;
#pragma unroll
            for (int mf = 0; mf < 2; mf++) {
                uint32_t ad = baseA + (uint32_t)((wy * 32 + mf * 16 + rsel) * ROWB) + kc2;
                ldsm4(ah[mf], ad);
                ldsm4(al[mf], ad + STG_SPLIT);
            }
#pragma unroll
            for (int p = 0; p < 4; p++) {
                uint32_t bd = baseB + (uint32_t)((wx * 64 + p * 16 + rsel) * ROWB) + kc2;
                ldsm4(bh[p], bd);
                ldsm4(bl[p], bd + STG_SPLIT);
            }
#pragma unroll
            for (int mf = 0; mf < 2; mf++)
#pragma unroll
                for (int p = 0; p < 4; p++)
#pragma unroll
                    for (int half = 0; half < 2; half++) {
                        float* d = acc[mf][p * 2 + half];
                        mma16816(d, ah[mf], bh[p][half], bh[p][2 + half]);
                        mma16816(d, ah[mf], bl[p][half], bl[p][2 + half]);
                        mma16816(d, al[mf], bh[p][half], bh[p][2 + half]);
                    }
        }
        __syncthreads();
        buf ^= 1;
    }

    // epilogue: fragment-direct scatter with bias
    const float* bias = args.bias[z] + (size_t)t * DD + y0;
    float* out = args.out[z];
#pragma unroll
    for (int mf = 0; mf < 2; mf++) {
        int mr = wy * 32 + mf * 16 + (lane >> 2);
        int nd0 = s_nodes[mr];
        int nd1 = s_nodes[mr + 8];
        float* o0 = (nd0 >= 0) ? (out + (size_t)nd0 * DD + y0) : nullptr;
        float* o1 = (nd1 >= 0) ? (out + (size_t)nd1 * DD + y0) : nullptr;
#pragma unroll
        for (int nf = 0; nf < 8; nf++) {
            int col = wx * 64 + nf * 8 + (lane & 3) * 2;
            float bx = bias[col], by = bias[col + 1];
            if (o0) *(float2*)(o0 + col) = make_float2(acc[mf][nf][0] + bx, acc[mf][nf][1] + by);
            if (o1) *(float2*)(o1 + col) = make_float2(acc[mf][nf][2] + bx, acc[mf][nf][3] + by);
        }
    }
}

// ---------------- relation transforms (FFMA2 GEMM, A-tile reused across relations) ------
__global__ __launch_bounds__(256) void rel_transform(const float* __restrict__ Watt,
                                                     const float* __restrict__ Wmsg,
                                                     int n) {
    extern __shared__ float sm[];
    float (*As)[264] = (float (*)[264])sm;
    float (*Bs)[64]  = (float (*)[64])(sm + 64 * 264);

    int tid = threadIdx.x;
    int z = blockIdx.z;
    int phase = z >> 2;
    int h = z & 3;

    const float* src   = phase ? g_v : g_k;
    const float* Wbase = phase ? Wmsg : Watt;
    float* dst         = phase ? g_vrel : g_krel;

    int row0 = blockIdx.x * 256;
    int tx = tid & 7, ty = tid >> 3;

    {
        int node = row0 + tid;
        if (node < n) {
            const float* Arow = src + (size_t)node * DD + h * DKK;
#pragma unroll
            for (int i = 0; i < 16; i++) {
                float4 v = *(const float4*)(Arow + i * 4);
                As[i * 4 + 0][tid] = v.x;
                As[i * 4 + 1][tid] = v.y;
                As[i * 4 + 2][tid] = v.z;
                As[i * 4 + 3][tid] = v.w;
            }
        } else {
#pragma unroll
            for (int i = 0; i < 64; i++) As[i][tid] = 0.f;
        }
    }

    for (int r = 0; r < RR; r++) {
        __syncthreads();
        const float* Wp = Wbase + ((size_t)r * HH + h) * DKK * DKK;
        for (int i = tid; i < DKK * DKK / 4; i += 256)
            ((float4*)Bs)[i] = ((const float4*)Wp)[i];
        __syncthreads();

        u64 acc[8][4];
#pragma unroll
        for (int i = 0; i < 8; i++)
#pragma unroll
            for (int j = 0; j < 4; j++) acc[i][j] = 0ull;

#pragma unroll 16
        for (int kk = 0; kk < DKK; kk++) {
            float4 a0 = *(float4*)&As[kk][ty * 8];
            float4 a1 = *(float4*)&As[kk][ty * 8 + 4];
            ulonglong2 blv = *(ulonglong2*)&Bs[kk][tx * 8];
            ulonglong2 bhv = *(ulonglong2*)&Bs[kk][tx * 8 + 4];
            u64 bb[4] = {blv.x, blv.y, bhv.x, bhv.y};
            float a[8] = {a0.x, a0.y, a0.z, a0.w, a1.x, a1.y, a1.z, a1.w};
#pragma unroll
            for (int i = 0; i < 8; i++) {
                u64 aa = splat2(a[i]);
                ffma2(acc[i][0], aa, bb[0]);
                ffma2(acc[i][1], aa, bb[1]);
                ffma2(acc[i][2], aa, bb[2]);
                ffma2(acc[i][3], aa, bb[3]);
            }
        }

#pragma unroll
        for (int i = 0; i < 8; i++) {
            int node = row0 + ty * 8 + i;
            if (node < n) {
                float* o = dst + ((size_t)r * n + node) * DD + h * DKK + tx * 8;
                float2 p0 = unpack2(acc[i][0]);
                float2 p1 = unpack2(acc[i][1]);
                float2 p2 = unpack2(acc[i][2]);
                float2 p3 = unpack2(acc[i][3]);
                *(float4*)o       = make_float4(p0.x, p0.y, p1.x, p1.y);
                *(float4*)(o + 4) = make_float4(p2.x, p2.y, p3.x, p3.y);
            }
        }
    }
}

// ---------------- edge pass 1 ----------------
__global__ void edge_att(const int* __restrict__ esrc, const int* __restrict__ edst,
                         const int* __restrict__ etype, const float* __restrict__ rel_pri,
                         int ne, int n) {
    int e = blockIdx.x * 8 + (threadIdx.x >> 5);
    if (e >= ne) return;
    int L = threadIdx.x & 31;
    int src = esrc[e], dst = edst[e], r = etype[e];

    const float4* qp = (const float4*)(g_q + (size_t)dst * DD) + L * 2;
    const float4* kp = (const float4*)(g_krel + ((size_t)r * n + src) * DD) + L * 2;
    float4 q0 = qp[0], q1 = qp[1];
    float4 k0 = kp[0], k1 = kp[1];
    float s = q0.x * k0.x + q0.y * k0.y + q0.z * k0.z + q0.w * k0.w
            + q1.x * k1.x + q1.y * k1.y + q1.z * k1.z + q1.w * k1.w;
    s += __shfl_xor_sync(0xffffffffu, s, 1);
    s += __shfl_xor_sync(0xffffffffu, s, 2);
    s += __shfl_xor_sync(0xffffffffu, s, 4);
    if ((L & 7) == 0) {
        int h = L >> 3;
        float att = s * rel_pri[r * HH + h] * 0.125f;
        float ex = expf(att);
        g_ex[(size_t)e * HH + h] = ex;
        atomicAdd(&g_denom[((size_t)dst * RR + r) * HH + h], ex);
    }
}

// ---------------- edge pass 2 ----------------
__global__ void edge_aggregate(const int* __restrict__ esrc, const int* __restrict__ edst,
                               const int* __restrict__ etype, int ne, int n) {
    int e = blockIdx.x * 8 + (threadIdx.x >> 5);
    if (e >= ne) return;
    int L = threadIdx.x & 31;
    int src = esrc[e], dst = edst[e], r = etype[e];
    int h = L >> 3;
    float w = g_ex[(size_t)e * HH + h] / g_denom[((size_t)dst * RR + r) * HH + h];

    const float4* vp = (const float4*)(g_vrel + ((size_t)r * n + src) * DD) + L * 2;
    float4 v0 = vp[0], v1 = vp[1];
    float* tp = g_t + (size_t)dst * DD + L * 8;
    asm volatile("red.global.add.v4.f32 [%0], {%1,%2,%3,%4};"
                 :: "l"(tp), "f"(v0.x * w), "f"(v0.y * w), "f"(v0.z * w), "f"(v0.w * w)
                 : "memory");
    asm volatile("red.global.add.v4.f32 [%0], {%1,%2,%3,%4};"
                 :: "l"(tp + 4), "f"(v1.x * w), "f"(v1.y * w), "f"(v1.z * w), "f"(v1.w * w)
                 : "memory");
}

// ---------------- per-node nrel ----------------
__global__ void node_nrel(int n) {
    int i = blockIdx.x * blockDim.x + threadIdx.x;
    if (i >= n) return;
    int c = 0;
#pragma unroll
    for (int r = 0; r < RR; r++)
        c += (g_denom[((size_t)i * RR + r) * HH] > 0.f) ? 1 : 0;
    g_hasmsg[i] = (c > 0) ? 1 : 0;
    g_invnrel[i] = 1.0f / (float)(c > 0 ? c : 1);
}

// ---------------- final: gated residual + LN + passthrough ----------------
__global__ void finalize(const float* __restrict__ x, const float* __restrict__ skip,
                         const float* __restrict__ ln_g, const float* __restrict__ ln_b,
                         const int* __restrict__ nt, float* __restrict__ out, int n) {
    int node = blockIdx.x * 8 + (threadIdx.x >> 5);
    if (node >= n) return;
    int L = threadIdx.x & 31;
    int t = nt[node];
    float alpha = 1.0f / (1.0f + expf(-skip[t]));
    float beta = 1.0f - alpha;

    const float4* xp = (const float4*)(x + (size_t)node * DD) + L * 2;
    const float4* tp = (const float4*)(g_trans + (size_t)node * DD) + L * 2;
    float4 x0 = xp[0], x1 = xp[1];
    float4 t0 = tp[0], t1 = tp[1];

    float o[8];
    o[0] = t0.x * alpha + x0.x * beta;
    o[1] = t0.y * alpha + x0.y * beta;
    o[2] = t0.z * alpha + x0.z * beta;
    o[3] = t0.w * alpha + x0.w * beta;
    o[4] = t1.x * alpha + x1.x * beta;
    o[5] = t1.y * alpha + x1.y * beta;
    o[6] = t1.z * alpha + x1.z * beta;
    o[7] = t1.w * alpha + x1.w * beta;

    float s = 0.f, s2 = 0.f;
#pragma unroll
    for (int j = 0; j < 8; j++) { s += o[j]; s2 += o[j] * o[j]; }
#pragma unroll
    for (int off = 16; off > 0; off >>= 1) {
        s  += __shfl_xor_sync(0xffffffffu, s, off);
        s2 += __shfl_xor_sync(0xffffffffu, s2, off);
    }
    float mu = s * (1.0f / DD);
    float var = s2 * (1.0f / DD) - mu * mu;
    float rstd = rsqrtf(var + 1e-5f);

    float4 r0, r1;
    if (g_hasmsg[node]) {
        const float4* gp = (const float4*)(ln_g + (size_t)t * DD) + L * 2;
        const float4* bp = (const float4*)(ln_b + (size_t)t * DD) + L * 2;
        float4 g0 = gp[0], g1 = gp[1];
        float4 b0 = bp[0], b1 = bp[1];
        r0.x = (o[0] - mu) * rstd * g0.x + b0.x;
        r0.y = (o[1] - mu) * rstd * g0.y + b0.y;
        r0.z = (o[2] - mu) * rstd * g0.z + b0.z;
        r0.w = (o[3] - mu) * rstd * g0.w + b0.w;
        r1.x = (o[4] - mu) * rstd * g1.x + b1.x;
        r1.y = (o[5] - mu) * rstd * g1.y + b1.y;
        r1.z = (o[6] - mu) * rstd * g1.z + b1.z;
        r1.w = (o[7] - mu) * rstd * g1.w + b1.w;
    } else {
        r0 = x0; r1 = x1;
    }
    float4* op = (float4*)(out + (size_t)node * DD) + L * 2;
    op[0] = r0;
    op[1] = r1;
}

// ---------------- host launcher ----------------
extern "C" void kernel_launch(void* const* d_in, const int* in_sizes, int n_in,
                              void* d_out, int out_size) {
    const float* x       = (const float*)d_in[0];
    const float* Wk      = (const float*)d_in[1];
    const float* bk      = (const float*)d_in[2];
    const float* Wq      = (const float*)d_in[3];
    const float* bq      = (const float*)d_in[4];
    const float* Wv      = (const float*)d_in[5];
    const float* bv      = (const float*)d_in[6];
    const float* Wa      = (const float*)d_in[7];
    const float* ba      = (const float*)d_in[8];
    const float* rel_pri = (const float*)d_in[9];
    const float* rel_att = (const float*)d_in[10];
    const float* rel_msg = (const float*)d_in[11];
    const float* skip    = (const float*)d_in[12];
    const float* ln_g    = (const float*)d_in[13];
    const float* ln_b    = (const float*)d_in[14];
    const int* node_type = (const int*)d_in[15];
    const int* edge_src  = (const int*)d_in[16];
    const int* edge_dst  = (const int*)d_in[17];
    const int* edge_type = (const int*)d_in[18];

    int n  = in_sizes[0] / DD;
    int ne = in_sizes[16];
    if (n > NN || ne > EE) return;

    void *p_cnt, *p_cursor, *p_perm, *p_denom, *p_t;
    void *p_k, *p_q, *p_v, *p_trans, *p_invnrel;
    void *p_xhi, *p_xlo, *p_thi, *p_tlo, *p_whiT, *p_wloT;
    cudaGetSymbolAddress(&p_cnt, g_cnt);
    cudaGetSymbolAddress(&p_cursor, g_cursor);
    cudaGetSymbolAddress(&p_perm, g_perm);
    cudaGetSymbolAddress(&p_denom, g_denom);
    cudaGetSymbolAddress(&p_t, g_t);
    cudaGetSymbolAddress(&p_k, g_k);
    cudaGetSymbolAddress(&p_q, g_q);
    cudaGetSymbolAddress(&p_v, g_v);
    cudaGetSymbolAddress(&p_trans, g_trans);
    cudaGetSymbolAddress(&p_invnrel, g_invnrel);
    cudaGetSymbolAddress(&p_xhi, g_xhi);
    cudaGetSymbolAddress(&p_xlo, g_xlo);
    cudaGetSymbolAddress(&p_thi, g_thi);
    cudaGetSymbolAddress(&p_tlo, g_tlo);
    cudaGetSymbolAddress(&p_whiT, g_whiT);
    cudaGetSymbolAddress(&p_wloT, g_wloT);

    cudaMemsetAsync(p_cnt, 0, sizeof(int) * TT);
    cudaMemsetAsync(p_cursor, 0, sizeof(int) * TT);
    cudaMemsetAsync(p_perm, 0xFF, sizeof(int) * NPADMAX);
    cudaMemsetAsync(p_denom, 0, sizeof(float) * (size_t)n * RR * HH);
    cudaMemsetAsync(p_t, 0, sizeof(float) * (size_t)n * DD);

    // conversions + bucketing
    conv_w<<<(4 * TT * DD * DD + 255) / 256, 256>>>(Wk, Wq, Wv, Wa);
    conv_split<<<(int)(((size_t)n * 128 + 255) / 256), 256>>>(x, nullptr,
        (__nv_bfloat16*)p_xhi, (__nv_bfloat16*)p_xlo, n);
    count_types<<<(n + 255) / 256, 256>>>(node_type, n);
    make_offsets<<<1, 1>>>();
    scatter_perm<<<(n + 255) / 256, 256>>>(node_type, n);

    cudaFuncSetAttribute(typed_gemm_tc, cudaFuncAttributeMaxDynamicSharedMemorySize, 2 * STG_BUF);

    // fused KQV typed linears on tensor cores (mma.sync)
    TcArgs a1;
    a1.Ahi = (const __nv_bfloat16*)p_xhi;
    a1.Alo = (const __nv_bfloat16*)p_xlo;
    for (int m = 0; m < 3; m++) {
        a1.WhiT[m] = (const __nv_bfloat16*)p_whiT + (size_t)m * TT * DD * DD;
        a1.WloT[m] = (const __nv_bfloat16*)p_wloT + (size_t)m * TT * DD * DD;
    }
    a1.bias[0] = bk; a1.bias[1] = bq; a1.bias[2] = bv;
    a1.out[0] = (float*)p_k; a1.out[1] = (float*)p_q; a1.out[2] = (float*)p_v;
    dim3 grid1((n + 127) / 128 + TT, DD / 128, 3);
    typed_gemm_tc<<<grid1, 256, 2 * STG_BUF>>>(a1);

    // relation transforms
    int relSmem = (64 * 264 + 64 * 64) * sizeof(float);
    cudaFuncSetAttribute(rel_transform, cudaFuncAttributeMaxDynamicSharedMemorySize, relSmem);
    dim3 gridR((n + 255) / 256, 1, 2 * HH);
    rel_transform<<<gridR, 256, relSmem>>>(rel_att, rel_msg, n);

    // edge passes
    edge_att<<<(ne + 7) / 8, 256>>>(edge_src, edge_dst, edge_type, rel_pri, ne, n);
    edge_aggregate<<<(ne + 7) / 8, 256>>>(edge_src, edge_dst, edge_type, ne, n);
    node_nrel<<<(n + 255) / 256, 256>>>(n);

    // output typed linear (invnrel folded into t conversion)
    conv_split<<<(int)(((size_t)n * 128 + 255) / 256), 256>>>((const float*)p_t, (const float*)p_invnrel,
        (__nv_bfloat16*)p_thi, (__nv_bfloat16*)p_tlo, n);
    TcArgs a2;
    a2.Ahi = (const __nv_bfloat16*)p_thi;
    a2.Alo = (const __nv_bfloat16*)p_tlo;
    for (int m = 0; m < 3; m++) {
        a2.WhiT[m] = (const __nv_bfloat16*)p_whiT + (size_t)3 * TT * DD * DD;
        a2.WloT[m] = (const __nv_bfloat16*)p_wloT + (size_t)3 * TT * DD * DD;
        a2.bias[m] = ba;
        a2.out[m] = (float*)p_trans;
    }
    dim3 grid2((n + 127) / 128 + TT, DD / 128, 1);
    typed_gemm_tc<<<grid2, 256, 2 * STG_BUF>>>(a2);

    // gated residual + LN + passthrough
    finalize<<<(n + 7) / 8, 256>>>(x, skip, ln_g, ln_b, node_type, (float*)d_out, n);
}

// round 14
// speedup vs baseline: 1.4903x; 1.0017x over previous
#include <cuda_runtime.h>
#include <cuda_bf16.h>
#include <math.h>
#include <stdint.h>

#define TT 3
#define RR 6
#define HH 4
#define DKK 64
#define DD 256
#define NN 50000
#define EE 400000
#define NPADMAX (NN + TT * 128)

typedef unsigned long long u64;

// ---- packed f32x2 helpers (for rel_transform) ----
__device__ __forceinline__ u64 splat2(float x) {
    u64 r;
    asm("mov.b64 %0, {%1, %1};" : "=l"(r) : "r"(__float_as_uint(x)));
    return r;
}
__device__ __forceinline__ void ffma2(u64& d, u64 a, u64 b) {
    asm("fma.rn.f32x2 %0, %1, %2, %3;" : "=l"(d) : "l"(a), "l"(b), "l"(d));
}
__device__ __forceinline__ float2 unpack2(u64 v) {
    unsigned int lo, hi;
    asm("mov.b64 {%0, %1}, %2;" : "=r"(lo), "=r"(hi) : "l"(v));
    return make_float2(__uint_as_float(lo), __uint_as_float(hi));
}

// ---- mma.sync / ldmatrix / cp.async helpers (sm_80-era, legal on sm_103) ----
__device__ __forceinline__ uint32_t smem_to_u32(const void* p) {
    uint32_t a;
    asm("{ .reg .u64 t; cvta.to.shared.u64 t, %1; cvt.u32.u64 %0, t; }" : "=r"(a) : "l"(p));
    return a;
}
__device__ __forceinline__ void ldsm4(uint32_t r[4], uint32_t addr) {
    asm volatile("ldmatrix.sync.aligned.m8n8.x4.shared.b16 {%0,%1,%2,%3}, [%4];"
        : "=r"(r[0]), "=r"(r[1]), "=r"(r[2]), "=r"(r[3]) : "r"(addr));
}
__device__ __forceinline__ void mma16816(float d[4], const uint32_t a[4], uint32_t b0, uint32_t b1) {
    asm volatile("mma.sync.aligned.m16n8k16.row.col.f32.bf16.bf16.f32 "
        "{%0,%1,%2,%3}, {%4,%5,%6,%7}, {%8,%9}, {%0,%1,%2,%3};"
        : "+f"(d[0]), "+f"(d[1]), "+f"(d[2]), "+f"(d[3])
        : "r"(a[0]), "r"(a[1]), "r"(a[2]), "r"(a[3]), "r"(b0), "r"(b1));
}
__device__ __forceinline__ void cp_async16(uint32_t dst, const void* src, bool valid) {
    int sz = valid ? 16 : 0;
    asm volatile("cp.async.cg.shared.global [%0], [%1], 16, %2;"
                 :: "r"(dst), "l"(src), "r"(sz));
}
#define CP_COMMIT() asm volatile("cp.async.commit_group;" ::: "memory")
#define CP_WAIT1()  asm volatile("cp.async.wait_group 1;" ::: "memory")
#define CP_WAIT0()  asm volatile("cp.async.wait_group 0;" ::: "memory")

// ---------------- scratch (device globals) ----------------
__device__ float g_k[(size_t)NN * DD];
__device__ float g_q[(size_t)NN * DD];
__device__ float g_v[(size_t)NN * DD];
__device__ float g_t[(size_t)NN * DD];
__device__ float g_trans[(size_t)NN * DD];
__device__ float g_krel[(size_t)RR * NN * DD];
__device__ float g_vrel[(size_t)RR * NN * DD];
__device__ float g_ex[(size_t)EE * HH];
__device__ float g_denom[(size_t)NN * RR * HH];
__device__ float g_invnrel[NN];
__device__ int   g_hasmsg[NN];
__device__ int   g_perm[NPADMAX];
__device__ int   g_cnt[TT];
__device__ int   g_cursor[TT];
__device__ int   g_padoff[TT + 1];
// bf16 hi/lo split buffers
__device__ __nv_bfloat16 g_xhi[(size_t)NN * DD];
__device__ __nv_bfloat16 g_xlo[(size_t)NN * DD];
__device__ __nv_bfloat16 g_thi[(size_t)NN * DD];
__device__ __nv_bfloat16 g_tlo[(size_t)NN * DD];
__device__ __nv_bfloat16 g_whiT[(size_t)4 * TT * DD * DD];   // [mat][t][j][k]  (W transposed)
__device__ __nv_bfloat16 g_wloT[(size_t)4 * TT * DD * DD];

// ---------------- type bucketing ----------------
__global__ void count_types(const int* __restrict__ nt, int n) {
    int i = blockIdx.x * blockDim.x + threadIdx.x;
    if (i < n) atomicAdd(&g_cnt[nt[i]], 1);
}
__global__ void make_offsets() {
    if (threadIdx.x == 0 && blockIdx.x == 0) {
        int off = 0;
        for (int t = 0; t < TT; t++) {
            g_padoff[t] = off;
            off += ((g_cnt[t] + 127) >> 7) << 7;
        }
        g_padoff[TT] = off;
    }
}
__global__ void scatter_perm(const int* __restrict__ nt, int n) {
    int i = blockIdx.x * blockDim.x + threadIdx.x;
    if (i < n) {
        int t = nt[i];
        int pos = g_padoff[t] + atomicAdd(&g_cursor[t], 1);
        g_perm[pos] = i;
    }
}

// ---------------- bf16 hi/lo split conversions ----------------
__global__ void conv_split(const float* __restrict__ src, const float* __restrict__ scale,
                           __nv_bfloat16* __restrict__ hi, __nv_bfloat16* __restrict__ lo, int n) {
    size_t i = (size_t)blockIdx.x * blockDim.x + threadIdx.x;
    if (i >= (size_t)n * 128) return;
    int node = (int)(i >> 7);
    float s = scale ? scale[node] : 1.0f;
    float2 f = ((const float2*)src)[i];
    f.x *= s; f.y *= s;
    __nv_bfloat16 h0 = __float2bfloat16(f.x);
    __nv_bfloat16 h1 = __float2bfloat16(f.y);
    __nv_bfloat16 l0 = __float2bfloat16(f.x - __bfloat162float(h0));
    __nv_bfloat16 l1 = __float2bfloat16(f.y - __bfloat162float(h1));
    hi[i * 2] = h0; hi[i * 2 + 1] = h1;
    lo[i * 2] = l0; lo[i * 2 + 1] = l1;
}

__global__ void conv_w(const float* __restrict__ Wk, const float* __restrict__ Wq,
                       const float* __restrict__ Wv, const float* __restrict__ Wa) {
    size_t i = (size_t)blockIdx.x * blockDim.x + threadIdx.x;
    if (i >= (size_t)4 * TT * DD * DD) return;
    int j = (int)(i % DD);
    size_t r = i / DD;
    int k = (int)(r % DD); r /= DD;
    int t = (int)(r % TT);
    int mat = (int)(r / TT);
    const float* src = (mat == 0) ? Wk : (mat == 1) ? Wq : (mat == 2) ? Wv : Wa;
    float w = src[((size_t)t * DD + k) * DD + j];
    __nv_bfloat16 h = __float2bfloat16(w);
    __nv_bfloat16 l = __float2bfloat16(w - __bfloat162float(h));
    size_t di = (((size_t)mat * TT + t) * DD + j) * DD + k;   // transposed [j][k]
    g_whiT[di] = h;
    g_wloT[di] = l;
}

// ---------------- tensor-core typed linear (mma.sync bf16x3 split precision)
// out[n] = A[n] @ W[type(n)] + bias[type(n)];  D = Ahi*Bhi + Ahi*Blo + Alo*Bhi (fp32 acc).
// BM=128, BN=128, BK=32, 8 warps (4M x 2N), warp tile 32x64, cp.async double-buffered.
struct TcArgs {
    const __nv_bfloat16* Ahi;      // [n][256]
    const __nv_bfloat16* Alo;
    const __nv_bfloat16* WhiT[3];  // [t][j][k]
    const __nv_bfloat16* WloT[3];
    const float* bias[3];
    float*       out[3];
};

// smem layout per buffer (48KB): A at 0, B at 24KB.
//   tile(split, kstep, row, kcol): split*12288 + kstep*6144 + row*48 + kcol*2  bytes
//   (row pad 24 bf16 = 48B -> ldmatrix conflict-free: r*48 mod 128 distinct for 8 rows)
#define STG_BUF   49152
#define STG_BOFF  24576
#define STG_SPLIT 12288
#define STG_KST   6144
#define ROWB      48

__global__ __launch_bounds__(256) void typed_gemm_tc(TcArgs args) {
    extern __shared__ char smem[];
    __shared__ int s_nodes[128];

    int row0 = blockIdx.x * 128;
    if (row0 >= g_padoff[TT]) return;
    int t = 0;
#pragma unroll
    for (int tt = 0; tt < TT - 1; tt++)
        if (row0 >= g_padoff[tt + 1]) t = tt + 1;

    uint32_t smem_base = smem_to_u32(smem);
    int tid = threadIdx.x;
    int lane = tid & 31;
    int wid = tid >> 5;
    int wy = wid & 3, wx = wid >> 2;

    if (tid < 128) s_nodes[tid] = g_perm[row0 + tid];
    __syncthreads();

    int z = blockIdx.z;
    int y0 = blockIdx.y * 128;
    const __nv_bfloat16* WhiT = args.WhiT[z] + ((size_t)t * DD + y0) * DD;
    const __nv_bfloat16* WloT = args.WloT[z] + ((size_t)t * DD + y0) * DD;

    // staging: slot s in [0,512): row=s>>2, kstep=(s>>1)&1, u4=s&1 -> 16B each
    int srow = tid >> 1;             // thread's two slots share row? no: use slot = tid + i*256
    (void)srow;
    int nodeCache[2];
    {
        int s0 = tid, s1 = tid + 256;
        nodeCache[0] = s_nodes[s0 >> 2];
        nodeCache[1] = s_nodes[s1 >> 2];
    }

    auto stage = [&](int chunk, int buf) {
        uint32_t sb = smem_base + buf * STG_BUF;
        int k0 = chunk * 32;
#pragma unroll
        for (int i = 0; i < 2; i++) {
            int slot = tid + i * 256;
            int row = slot >> 2, kstep = (slot >> 1) & 1, u4 = slot & 1;
            int node = nodeCache[i];
            int ksub = k0 + kstep * 16 + u4 * 8;
            uint32_t dA = sb + kstep * STG_KST + row * ROWB + u4 * 16;
            const __nv_bfloat16* pa = args.Ahi + ((size_t)(node < 0 ? 0 : node) * DD + ksub);
            const __nv_bfloat16* pl = args.Alo + ((size_t)(node < 0 ? 0 : node) * DD + ksub);
            cp_async16(dA, pa, node >= 0);
            cp_async16(dA + STG_SPLIT, pl, node >= 0);
            uint32_t dB = sb + STG_BOFF + kstep * STG_KST + row * ROWB + u4 * 16;
            cp_async16(dB, WhiT + (size_t)row * DD + ksub, true);
            cp_async16(dB + STG_SPLIT, WloT + (size_t)row * DD + ksub, true);
        }
    };

    float acc[2][8][4];
#pragma unroll
    for (int a = 0; a < 2; a++)
#pragma unroll
        for (int b = 0; b < 8; b++)
#pragma unroll
            for (int c = 0; c < 4; c++) acc[a][b][c] = 0.f;

    stage(0, 0);
    CP_COMMIT();

    // ldmatrix lane addressing
    int rsel = (lane & 7) + ((lane >> 3) & 1) * 8;
    int kc2 = ((lane >> 4) & 1) * 16;   // byte offset of k-col (8 bf16)

    int buf = 0;
    for (int c = 0; c < 8; c++) {
        if (c < 7) { stage(c + 1, buf ^ 1); CP_COMMIT(); }
        if (c < 7) CP_WAIT1(); else CP_WAIT0();
        __syncthreads();

        uint32_t sb = smem_base + buf * STG_BUF;
#pragma unroll
        for (int kstep = 0; kstep < 2; kstep++) {
            uint32_t ah[2][4], al[2][4], bh[4][4], bl[4][4];
            uint32_t baseA = sb + kstep * STG_KST;
            uint32_t baseB = sb + STG_BOFF + kstep * STG_KST;
#pragma unroll
            for (int mf = 0; mf < 2; mf++) {
                uint32_t ad = baseA + (uint32_t)((wy * 32 + mf * 16 + rsel) * ROWB) + kc2;
                ldsm4(ah[mf], ad);
                ldsm4(al[mf], ad + STG_SPLIT);
            }
#pragma unroll
            for (int p = 0; p < 4; p++) {
                uint32_t bd = baseB + (uint32_t)((wx * 64 + p * 16 + rsel) * ROWB) + kc2;
                ldsm4(bh[p], bd);
                ldsm4(bl[p], bd + STG_SPLIT);
            }
#pragma unroll
            for (int mf = 0; mf < 2; mf++)
#pragma unroll
                for (int p = 0; p < 4; p++)
#pragma unroll
                    for (int half = 0; half < 2; half++) {
                        float* d = acc[mf][p * 2 + half];
                        mma16816(d, ah[mf], bh[p][half], bh[p][2 + half]);
                        mma16816(d, ah[mf], bl[p][half], bl[p][2 + half]);
                        mma16816(d, al[mf], bh[p][half], bh[p][2 + half]);
                    }
        }
        __syncthreads();
        buf ^= 1;
    }

    // epilogue: fragment-direct scatter with bias
    const float* bias = args.bias[z] + (size_t)t * DD + y0;
    float* out = args.out[z];
#pragma unroll
    for (int mf = 0; mf < 2; mf++) {
        int mr = wy * 32 + mf * 16 + (lane >> 2);
        int nd0 = s_nodes[mr];
        int nd1 = s_nodes[mr + 8];
        float* o0 = (nd0 >= 0) ? (out + (size_t)nd0 * DD + y0) : nullptr;
        float* o1 = (nd1 >= 0) ? (out + (size_t)nd1 * DD + y0) : nullptr;
#pragma unroll
        for (int nf = 0; nf < 8; nf++) {
            int col = wx * 64 + nf * 8 + (lane & 3) * 2;
            float bx = bias[col], by = bias[col + 1];
            if (o0) *(float2*)(o0 + col) = make_float2(acc[mf][nf][0] + bx, acc[mf][nf][1] + by);
            if (o1) *(float2*)(o1 + col) = make_float2(acc[mf][nf][2] + bx, acc[mf][nf][3] + by);
        }
    }
}

// ---------------- relation transforms (FFMA2 GEMM, A-tile reused across relations) ------
__global__ __launch_bounds__(256) void rel_transform(const float* __restrict__ Watt,
                                                     const float* __restrict__ Wmsg,
                                                     int n) {
    extern __shared__ float sm[];
    float (*As)[264] = (float (*)[264])sm;
    float (*Bs)[64]  = (float (*)[64])(sm + 64 * 264);

    int tid = threadIdx.x;
    int z = blockIdx.z;
    int phase = z >> 2;
    int h = z & 3;

    const float* src   = phase ? g_v : g_k;
    const float* Wbase = phase ? Wmsg : Watt;
    float* dst         = phase ? g_vrel : g_krel;

    int row0 = blockIdx.x * 256;
    int tx = tid & 7, ty = tid >> 3;

    {
        int node = row0 + tid;
        if (node < n) {
            const float* Arow = src + (size_t)node * DD + h * DKK;
#pragma unroll
            for (int i = 0; i < 16; i++) {
                float4 v = *(const float4*)(Arow + i * 4);
                As[i * 4 + 0][tid] = v.x;
                As[i * 4 + 1][tid] = v.y;
                As[i * 4 + 2][tid] = v.z;
                As[i * 4 + 3][tid] = v.w;
            }
        } else {
#pragma unroll
            for (int i = 0; i < 64; i++) As[i][tid] = 0.f;
        }
    }

    for (int r = 0; r < RR; r++) {
        __syncthreads();
        const float* Wp = Wbase + ((size_t)r * HH + h) * DKK * DKK;
        for (int i = tid; i < DKK * DKK / 4; i += 256)
            ((float4*)Bs)[i] = ((const float4*)Wp)[i];
        __syncthreads();

        u64 acc[8][4];
#pragma unroll
        for (int i = 0; i < 8; i++)
#pragma unroll
            for (int j = 0; j < 4; j++) acc[i][j] = 0ull;

#pragma unroll 16
        for (int kk = 0; kk < DKK; kk++) {
            float4 a0 = *(float4*)&As[kk][ty * 8];
            float4 a1 = *(float4*)&As[kk][ty * 8 + 4];
            ulonglong2 blv = *(ulonglong2*)&Bs[kk][tx * 8];
            ulonglong2 bhv = *(ulonglong2*)&Bs[kk][tx * 8 + 4];
            u64 bb[4] = {blv.x, blv.y, bhv.x, bhv.y};
            float a[8] = {a0.x, a0.y, a0.z, a0.w, a1.x, a1.y, a1.z, a1.w};
#pragma unroll
            for (int i = 0; i < 8; i++) {
                u64 aa = splat2(a[i]);
                ffma2(acc[i][0], aa, bb[0]);
                ffma2(acc[i][1], aa, bb[1]);
                ffma2(acc[i][2], aa, bb[2]);
                ffma2(acc[i][3], aa, bb[3]);
            }
        }

#pragma unroll
        for (int i = 0; i < 8; i++) {
            int node = row0 + ty * 8 + i;
            if (node < n) {
                float* o = dst + ((size_t)r * n + node) * DD + h * DKK + tx * 8;
                float2 p0 = unpack2(acc[i][0]);
                float2 p1 = unpack2(acc[i][1]);
                float2 p2 = unpack2(acc[i][2]);
                float2 p3 = unpack2(acc[i][3]);
                *(float4*)o       = make_float4(p0.x, p0.y, p1.x, p1.y);
                *(float4*)(o + 4) = make_float4(p2.x, p2.y, p3.x, p3.y);
            }
        }
    }
}

// ---------------- edge pass 1 ----------------
__global__ void edge_att(const int* __restrict__ esrc, const int* __restrict__ edst,
                         const int* __restrict__ etype, const float* __restrict__ rel_pri,
                         int ne, int n) {
    int e = blockIdx.x * 8 + (threadIdx.x >> 5);
    if (e >= ne) return;
    int L = threadIdx.x & 31;
    int src = esrc[e], dst = edst[e], r = etype[e];

    const float4* qp = (const float4*)(g_q + (size_t)dst * DD) + L * 2;
    const float4* kp = (const float4*)(g_krel + ((size_t)r * n + src) * DD) + L * 2;
    float4 q0 = qp[0], q1 = qp[1];
    float4 k0 = kp[0], k1 = kp[1];
    float s = q0.x * k0.x + q0.y * k0.y + q0.z * k0.z + q0.w * k0.w
            + q1.x * k1.x + q1.y * k1.y + q1.z * k1.z + q1.w * k1.w;
    s += __shfl_xor_sync(0xffffffffu, s, 1);
    s += __shfl_xor_sync(0xffffffffu, s, 2);
    s += __shfl_xor_sync(0xffffffffu, s, 4);
    if ((L & 7) == 0) {
        int h = L >> 3;
        float att = s * rel_pri[r * HH + h] * 0.125f;
        float ex = expf(att);
        g_ex[(size_t)e * HH + h] = ex;
        atomicAdd(&g_denom[((size_t)dst * RR + r) * HH + h], ex);
    }
}

// ---------------- edge pass 2 ----------------
__global__ void edge_aggregate(const int* __restrict__ esrc, const int* __restrict__ edst,
                               const int* __restrict__ etype, int ne, int n) {
    int e = blockIdx.x * 8 + (threadIdx.x >> 5);
    if (e >= ne) return;
    int L = threadIdx.x & 31;
    int src = esrc[e], dst = edst[e], r = etype[e];
    int h = L >> 3;
    float w = g_ex[(size_t)e * HH + h] / g_denom[((size_t)dst * RR + r) * HH + h];

    const float4* vp = (const float4*)(g_vrel + ((size_t)r * n + src) * DD) + L * 2;
    float4 v0 = vp[0], v1 = vp[1];
    float* tp = g_t + (size_t)dst * DD + L * 8;
    asm volatile("red.global.add.v4.f32 [%0], {%1,%2,%3,%4};"
                 :: "l"(tp), "f"(v0.x * w), "f"(v0.y * w), "f"(v0.z * w), "f"(v0.w * w)
                 : "memory");
    asm volatile("red.global.add.v4.f32 [%0], {%1,%2,%3,%4};"
                 :: "l"(tp + 4), "f"(v1.x * w), "f"(v1.y * w), "f"(v1.z * w), "f"(v1.w * w)
                 : "memory");
}

// ---------------- per-node nrel ----------------
__global__ void node_nrel(int n) {
    int i = blockIdx.x * blockDim.x + threadIdx.x;
    if (i >= n) return;
    int c = 0;
#pragma unroll
    for (int r = 0; r < RR; r++)
        c += (g_denom[((size_t)i * RR + r) * HH] > 0.f) ? 1 : 0;
    g_hasmsg[i] = (c > 0) ? 1 : 0;
    g_invnrel[i] = 1.0f / (float)(c > 0 ? c : 1);
}

// ---------------- final: gated residual + LN + passthrough ----------------
__global__ void finalize(const float* __restrict__ x, const float* __restrict__ skip,
                         const float* __restrict__ ln_g, const float* __restrict__ ln_b,
                         const int* __restrict__ nt, float* __restrict__ out, int n) {
    int node = blockIdx.x * 8 + (threadIdx.x >> 5);
    if (node >= n) return;
    int L = threadIdx.x & 31;
    int t = nt[node];
    float alpha = 1.0f / (1.0f + expf(-skip[t]));
    float beta = 1.0f - alpha;

    const float4* xp = (const float4*)(x + (size_t)node * DD) + L * 2;
    const float4* tp = (const float4*)(g_trans + (size_t)node * DD) + L * 2;
    float4 x0 = xp[0], x1 = xp[1];
    float4 t0 = tp[0], t1 = tp[1];

    float o[8];
    o[0] = t0.x * alpha + x0.x * beta;
    o[1] = t0.y * alpha + x0.y * beta;
    o[2] = t0.z * alpha + x0.z * beta;
    o[3] = t0.w * alpha + x0.w * beta;
    o[4] = t1.x * alpha + x1.x * beta;
    o[5] = t1.y * alpha + x1.y * beta;
    o[6] = t1.z * alpha + x1.z * beta;
    o[7] = t1.w * alpha + x1.w * beta;

    float s = 0.f, s2 = 0.f;
#pragma unroll
    for (int j = 0; j < 8; j++) { s += o[j]; s2 += o[j] * o[j]; }
#pragma unroll
    for (int off = 16; off > 0; off >>= 1) {
        s  += __shfl_xor_sync(0xffffffffu, s, off);
        s2 += __shfl_xor_sync(0xffffffffu, s2, off);
    }
    float mu = s * (1.0f / DD);
    float var = s2 * (1.0f / DD) - mu * mu;
    float rstd = rsqrtf(var + 1e-5f);

    float4 r0, r1;
    if (g_hasmsg[node]) {
        const float4* gp = (const float4*)(ln_g + (size_t)t * DD) + L * 2;
        const float4* bp = (const float4*)(ln_b + (size_t)t * DD) + L * 2;
        float4 g0 = gp[0], g1 = gp[1];
        float4 b0 = bp[0], b1 = bp[1];
        r0.x = (o[0] - mu) * rstd * g0.x + b0.x;
        r0.y = (o[1] - mu) * rstd * g0.y + b0.y;
        r0.z = (o[2] - mu) * rstd * g0.z + b0.z;
        r0.w = (o[3] - mu) * rstd * g0.w + b0.w;
        r1.x = (o[4] - mu) * rstd * g1.x + b1.x;
        r1.y = (o[5] - mu) * rstd * g1.y + b1.y;
        r1.z = (o[6] - mu) * rstd * g1.z + b1.z;
        r1.w = (o[7] - mu) * rstd * g1.w + b1.w;
    } else {
        r0 = x0; r1 = x1;
    }
    float4* op = (float4*)(out + (size_t)node * DD) + L * 2;
    op[0] = r0;
    op[1] = r1;
}

// ---------------- host launcher ----------------
extern "C" void kernel_launch(void* const* d_in, const int* in_sizes, int n_in,
                              void* d_out, int out_size) {
    const float* x       = (const float*)d_in[0];
    const float* Wk      = (const float*)d_in[1];
    const float* bk      = (const float*)d_in[2];
    const float* Wq      = (const float*)d_in[3];
    const float* bq      = (const float*)d_in[4];
    const float* Wv      = (const float*)d_in[5];
    const float* bv      = (const float*)d_in[6];
    const float* Wa      = (const float*)d_in[7];
    const float* ba      = (const float*)d_in[8];
    const float* rel_pri = (const float*)d_in[9];
    const float* rel_att = (const float*)d_in[10];
    const float* rel_msg = (const float*)d_in[11];
    const float* skip    = (const float*)d_in[12];
    const float* ln_g    = (const float*)d_in[13];
    const float* ln_b    = (const float*)d_in[14];
    const int* node_type = (const int*)d_in[15];
    const int* edge_src  = (const int*)d_in[16];
    const int* edge_dst  = (const int*)d_in[17];
    const int* edge_type = (const int*)d_in[18];

    int n  = in_sizes[0] / DD;
    int ne = in_sizes[16];
    if (n > NN || ne > EE) return;

    void *p_cnt, *p_cursor, *p_perm, *p_denom, *p_t;
    void *p_k, *p_q, *p_v, *p_trans, *p_invnrel;
    void *p_xhi, *p_xlo, *p_thi, *p_tlo, *p_whiT, *p_wloT;
    cudaGetSymbolAddress(&p_cnt, g_cnt);
    cudaGetSymbolAddress(&p_cursor, g_cursor);
    cudaGetSymbolAddress(&p_perm, g_perm);
    cudaGetSymbolAddress(&p_denom, g_denom);
    cudaGetSymbolAddress(&p_t, g_t);
    cudaGetSymbolAddress(&p_k, g_k);
    cudaGetSymbolAddress(&p_q, g_q);
    cudaGetSymbolAddress(&p_v, g_v);
    cudaGetSymbolAddress(&p_trans, g_trans);
    cudaGetSymbolAddress(&p_invnrel, g_invnrel);
    cudaGetSymbolAddress(&p_xhi, g_xhi);
    cudaGetSymbolAddress(&p_xlo, g_xlo);
    cudaGetSymbolAddress(&p_thi, g_thi);
    cudaGetSymbolAddress(&p_tlo, g_tlo);
    cudaGetSymbolAddress(&p_whiT, g_whiT);
    cudaGetSymbolAddress(&p_wloT, g_wloT);

    cudaMemsetAsync(p_cnt, 0, sizeof(int) * TT);
    cudaMemsetAsync(p_cursor, 0, sizeof(int) * TT);
    cudaMemsetAsync(p_perm, 0xFF, sizeof(int) * NPADMAX);
    cudaMemsetAsync(p_denom, 0, sizeof(float) * (size_t)n * RR * HH);
    cudaMemsetAsync(p_t, 0, sizeof(float) * (size_t)n * DD);

    // conversions + bucketing
    conv_w<<<(4 * TT * DD * DD + 255) / 256, 256>>>(Wk, Wq, Wv, Wa);
    conv_split<<<(int)(((size_t)n * 128 + 255) / 256), 256>>>(x, nullptr,
        (__nv_bfloat16*)p_xhi, (__nv_bfloat16*)p_xlo, n);
    count_types<<<(n + 255) / 256, 256>>>(node_type, n);
    make_offsets<<<1, 1>>>();
    scatter_perm<<<(n + 255) / 256, 256>>>(node_type, n);

    cudaFuncSetAttribute(typed_gemm_tc, cudaFuncAttributeMaxDynamicSharedMemorySize, 2 * STG_BUF);

    // fused KQV typed linears on tensor cores (mma.sync)
    TcArgs a1;
    a1.Ahi = (const __nv_bfloat16*)p_xhi;
    a1.Alo = (const __nv_bfloat16*)p_xlo;
    for (int m = 0; m < 3; m++) {
        a1.WhiT[m] = (const __nv_bfloat16*)p_whiT + (size_t)m * TT * DD * DD;
        a1.WloT[m] = (const __nv_bfloat16*)p_wloT + (size_t)m * TT * DD * DD;
    }
    a1.bias[0] = bk; a1.bias[1] = bq; a1.bias[2] = bv;
    a1.out[0] = (float*)p_k; a1.out[1] = (float*)p_q; a1.out[2] = (float*)p_v;
    dim3 grid1((n + 127) / 128 + TT, DD / 128, 3);
    typed_gemm_tc<<<grid1, 256, 2 * STG_BUF>>>(a1);

    // relation transforms
    int relSmem = (64 * 264 + 64 * 64) * sizeof(float);
    cudaFuncSetAttribute(rel_transform, cudaFuncAttributeMaxDynamicSharedMemorySize, relSmem);
    dim3 gridR((n + 255) / 256, 1, 2 * HH);
    rel_transform<<<gridR, 256, relSmem>>>(rel_att, rel_msg, n);

    // edge passes
    edge_att<<<(ne + 7) / 8, 256>>>(edge_src, edge_dst, edge_type, rel_pri, ne, n);
    edge_aggregate<<<(ne + 7) / 8, 256>>>(edge_src, edge_dst, edge_type, ne, n);
    node_nrel<<<(n + 255) / 256, 256>>>(n);

    // output typed linear (invnrel folded into t conversion)
    conv_split<<<(int)(((size_t)n * 128 + 255) / 256), 256>>>((const float*)p_t, (const float*)p_invnrel,
        (__nv_bfloat16*)p_thi, (__nv_bfloat16*)p_tlo, n);
    TcArgs a2;
    a2.Ahi = (const __nv_bfloat16*)p_thi;
    a2.Alo = (const __nv_bfloat16*)p_tlo;
    for (int m = 0; m < 3; m++) {
        a2.WhiT[m] = (const __nv_bfloat16*)p_whiT + (size_t)3 * TT * DD * DD;
        a2.WloT[m] = (const __nv_bfloat16*)p_wloT + (size_t)3 * TT * DD * DD;
        a2.bias[m] = ba;
        a2.out[m] = (float*)p_trans;
    }
    dim3 grid2((n + 127) / 128 + TT, DD / 128, 1);
    typed_gemm_tc<<<grid2, 256, 2 * STG_BUF>>>(a2);

    // gated residual + LN + passthrough
    finalize<<<(n + 7) / 8, 256>>>(x, skip, ln_g, ln_b, node_type, (float*)d_out, n);
}